// round 2
// baseline (speedup 1.0000x reference)
#include <cuda_runtime.h>

#define NF 40
#define NP 780      // 40*39/2 pairs
#define ED 64
#define AS 32
#define THREADS 256
#define XPITCH 65   // padded row pitch for xs to avoid bank conflicts

__global__ __launch_bounds__(THREADS) void afm_kernel(
    const float* __restrict__ x,
    const float* __restrict__ attn_w,
    const float* __restrict__ attn_b,
    const float* __restrict__ proj_w,
    const float* __restrict__ proj_b,
    const float* __restrict__ fc_w,
    const float* __restrict__ fc_b,
    float* __restrict__ out)
{
    __shared__ float xs[NF * XPITCH];                 // 10400 B
    __shared__ __align__(16) float Ws[ED * AS];       // 8192 B, row-major [d][a]
    __shared__ float logits_s[NP];                    // 3120 B
    __shared__ unsigned char pi_s[NP], pj_s[NP];      // 1560 B
    __shared__ float pw_s[AS], ab_s[AS], fw_s[ED];
    __shared__ float rmax[8], rsum[8];
    __shared__ float part[8 * 64];                    // per-warp partial attn_out
    __shared__ float red_s[64];

    const int tid  = threadIdx.x;
    const int lane = tid & 31;
    const int wid  = tid >> 5;
    const int b    = blockIdx.x;

    // ---- Phase 1: stage inputs into smem ----
    const float* xb = x + (long long)b * (NF * ED);
    for (int idx = tid; idx < NF * ED; idx += THREADS)
        xs[(idx >> 6) * XPITCH + (idx & 63)] = xb[idx];
    for (int idx = tid; idx < ED * AS; idx += THREADS)
        Ws[idx] = attn_w[idx];
    if (tid < AS) { pw_s[tid] = proj_w[tid]; ab_s[tid] = attn_b[tid]; }
    if (tid < ED) fw_s[tid] = fc_w[tid];

    // pair -> (i, j) table (upper triangle, row-major, matches np.triu_indices)
    for (int p = tid; p < NP; p += THREADS) {
        int i = 0, rem = p;
        while (rem >= NF - 1 - i) { rem -= NF - 1 - i; ++i; }
        pi_s[p] = (unsigned char)i;
        pj_s[p] = (unsigned char)(i + 1 + rem);
    }
    const float pb = proj_b[0];
    __syncthreads();

    // ---- Phase 2: per-pair GEMM, 2 pairs per thread to amortize W-row loads ----
    for (int base = 0; base < NP; base += 2 * THREADS) {
        const int pA = base + tid;             // always < NP for our sizes
        const int pB = base + THREADS + tid;
        const bool vB = (pB < NP);

        const int ibA = pi_s[pA] * XPITCH;
        const int jbA = pj_s[pA] * XPITCH;
        const int ibB = vB ? pi_s[pB] * XPITCH : 0;
        const int jbB = vB ? pj_s[pB] * XPITCH : 0;

        unsigned long long hA[16], hB[16];
#pragma unroll
        for (int k = 0; k < 16; ++k) {
            unsigned long long bias;
            asm("mov.b64 %0, {%1, %2};"
                : "=l"(bias) : "f"(ab_s[2 * k]), "f"(ab_s[2 * k + 1]));
            hA[k] = bias;
            hB[k] = bias;
        }

#pragma unroll 2
        for (int d = 0; d < ED; ++d) {
            float ipA = xs[ibA + d] * xs[jbA + d];
            float ipB = xs[ibB + d] * xs[jbB + d];
            unsigned long long ip2A, ip2B;
            asm("mov.b64 %0, {%1, %1};" : "=l"(ip2A) : "f"(ipA));
            asm("mov.b64 %0, {%1, %1};" : "=l"(ip2B) : "f"(ipB));
            const ulonglong2* Wv = reinterpret_cast<const ulonglong2*>(Ws + d * AS);
#pragma unroll
            for (int k = 0; k < 16; k += 2) {
                ulonglong2 w = Wv[k >> 1];   // warp-uniform address -> broadcast
                asm("fma.rn.f32x2 %0, %1, %2, %0;" : "+l"(hA[k])     : "l"(ip2A), "l"(w.x));
                asm("fma.rn.f32x2 %0, %1, %2, %0;" : "+l"(hA[k + 1]) : "l"(ip2A), "l"(w.y));
                asm("fma.rn.f32x2 %0, %1, %2, %0;" : "+l"(hB[k])     : "l"(ip2B), "l"(w.x));
                asm("fma.rn.f32x2 %0, %1, %2, %0;" : "+l"(hB[k + 1]) : "l"(ip2B), "l"(w.y));
            }
        }

        float logitA = pb, logitB = pb;
#pragma unroll
        for (int k = 0; k < 16; ++k) {
            float a0, a1, b0, b1;
            asm("mov.b64 {%0, %1}, %2;" : "=f"(a0), "=f"(a1) : "l"(hA[k]));
            asm("mov.b64 {%0, %1}, %2;" : "=f"(b0), "=f"(b1) : "l"(hB[k]));
            logitA += fmaxf(a0, 0.f) * pw_s[2 * k] + fmaxf(a1, 0.f) * pw_s[2 * k + 1];
            logitB += fmaxf(b0, 0.f) * pw_s[2 * k] + fmaxf(b1, 0.f) * pw_s[2 * k + 1];
        }
        logits_s[pA] = logitA;
        if (vB) logits_s[pB] = logitB;
    }
    __syncthreads();

    // ---- Phase 3: softmax over the 780 pairs (unnormalized; fold 1/S at the end) ----
    float lm = -3.4e38f;
    for (int p = tid; p < NP; p += THREADS) lm = fmaxf(lm, logits_s[p]);
#pragma unroll
    for (int o = 16; o > 0; o >>= 1) lm = fmaxf(lm, __shfl_xor_sync(0xffffffffu, lm, o));
    if (lane == 0) rmax[wid] = lm;
    __syncthreads();

    float gmax = rmax[0];
#pragma unroll
    for (int w = 1; w < 8; ++w) gmax = fmaxf(gmax, rmax[w]);

    float ls = 0.f;
    for (int p = tid; p < NP; p += THREADS) {
        float e = __expf(logits_s[p] - gmax);
        logits_s[p] = e;
        ls += e;
    }
#pragma unroll
    for (int o = 16; o > 0; o >>= 1) ls += __shfl_xor_sync(0xffffffffu, ls, o);
    if (lane == 0) rsum[wid] = ls;
    __syncthreads();

    // ---- Phase 4: weighted sum over pairs (recompute ip), then fc dot ----
    float accL = 0.f, accH = 0.f;
    for (int p = wid; p < NP; p += 8) {
        float s = logits_s[p];                  // broadcast
        int ib = pi_s[p] * XPITCH;
        int jb = pj_s[p] * XPITCH;
        accL += s * (xs[ib + lane]      * xs[jb + lane]);
        accH += s * (xs[ib + 32 + lane] * xs[jb + 32 + lane]);
    }
    part[wid * 64 + lane]      = accL;
    part[wid * 64 + 32 + lane] = accH;
    __syncthreads();

    if (tid < 64) {
        float v = 0.f;
#pragma unroll
        for (int w = 0; w < 8; ++w) v += part[w * 64 + tid];
        red_s[tid] = v * fw_s[tid];
    }
    __syncthreads();

    if (tid == 0) {
        float S = 0.f;
#pragma unroll
        for (int w = 0; w < 8; ++w) S += rsum[w];
        float t = 0.f;
#pragma unroll
        for (int k = 0; k < 64; ++k) t += red_s[k];
        out[b] = t / S + fc_b[0];
    }
}

extern "C" void kernel_launch(void* const* d_in, const int* in_sizes, int n_in,
                              void* d_out, int out_size)
{
    const float* x      = (const float*)d_in[0];
    const float* attn_w = (const float*)d_in[1];
    const float* attn_b = (const float*)d_in[2];
    const float* proj_w = (const float*)d_in[3];
    const float* proj_b = (const float*)d_in[4];
    const float* fc_w   = (const float*)d_in[5];
    const float* fc_b   = (const float*)d_in[6];
    float* out = (float*)d_out;

    afm_kernel<<<2048, THREADS>>>(x, attn_w, attn_b, proj_w, proj_b, fc_w, fc_b, out);
}

// round 4
// speedup vs baseline: 1.2066x; 1.2066x over previous
#include <cuda_runtime.h>
#include <cstdint>

#define NF 40
#define NP 780        // 40*39/2
#define ED 64
#define AS 32
#define THREADS 256
#define CP 128        // pairs per chunk
#define NCH 7         // ceil(780/128)
#define NPAD (NCH*CP) // 896

// ---- dynamic smem byte offsets (all 16B-aligned) ----
#define IP_OFF    0        // [64 d][128 pairs] f32        32768
#define XS_OFF    32768    // [40][65] f32 (pitch 65)      10432 (10400 used)
#define W2_OFF    43200    // [64 d][16 colpairs] u64       8192
#define OFFS_OFF  51392    // [896] u32 packed byte-offs    3584
#define LOG_OFF   54976    // [896] f32                     3584
#define PART_OFF  58560    // [128][9] f32                  4608
#define AB_OFF    63168    // 32 f32
#define PW_OFF    63296    // 32 f32
#define FW_OFF    63424    // 64 f32
#define RMAX_OFF  63680    // 8 f32
#define RSUM_OFF  63712    // 8 f32
#define RED_OFF   63744    // 64 f32
#define SMEM_TOTAL 64000

__device__ __forceinline__ unsigned long long pack2(float a, float b) {
    unsigned long long r;
    asm("mov.b64 %0, {%1, %2};" : "=l"(r) : "f"(a), "f"(b));
    return r;
}
__device__ __forceinline__ unsigned long long splat2(float a) {
    unsigned long long r;
    asm("mov.b64 %0, {%1, %1};" : "=l"(r) : "f"(a));
    return r;
}
__device__ __forceinline__ void unpack2(unsigned long long v, float& a, float& b) {
    asm("mov.b64 {%0, %1}, %2;" : "=f"(a), "=f"(b) : "l"(v));
}
#define FMA2(acc, a, b) asm("fma.rn.f32x2 %0, %1, %2, %0;" : "+l"(acc) : "l"(a), "l"(b))

__global__ __launch_bounds__(THREADS) void afm_kernel(
    const float* __restrict__ x,
    const float* __restrict__ attn_w,
    const float* __restrict__ attn_b,
    const float* __restrict__ proj_w,
    const float* __restrict__ proj_b,
    const float* __restrict__ fc_w,
    const float* __restrict__ fc_b,
    float* __restrict__ out)
{
    extern __shared__ char smem[];
    float* xs        = (float*)(smem + XS_OFF);
    float* logits_s  = (float*)(smem + LOG_OFF);
    float* part      = (float*)(smem + PART_OFF);
    float* ab_s      = (float*)(smem + AB_OFF);
    float* pw_s      = (float*)(smem + PW_OFF);
    float* fw_s      = (float*)(smem + FW_OFF);
    float* rmax      = (float*)(smem + RMAX_OFF);
    float* rsum      = (float*)(smem + RSUM_OFF);
    float* red_s     = (float*)(smem + RED_OFF);
    uint32_t* offs   = (uint32_t*)(smem + OFFS_OFF);

    const int tid  = threadIdx.x;
    const int lane = tid & 31;
    const int wid  = tid >> 5;
    const int b    = blockIdx.x;

    // ---- Phase 1: stage inputs ----
    const float* xb = x + (long long)b * (NF * ED);
    for (int idx = tid; idx < NF * ED; idx += THREADS)
        xs[(idx >> 6) * 65 + (idx & 63)] = xb[idx];

    // W packed f32x2: W2[d][cg] = (attn_w[d*32+2cg], attn_w[d*32+2cg+1])
    unsigned long long* W2 = (unsigned long long*)(smem + W2_OFF);
    for (int e = tid; e < ED * 16; e += THREADS) {
        const float2 wv = *(const float2*)(attn_w + e * 2);   // e*2 = d*32+2cg
        W2[e] = pack2(wv.x, wv.y);
    }

    if (tid < AS) { pw_s[tid] = proj_w[tid]; ab_s[tid] = attn_b[tid]; }
    if (tid < ED) fw_s[tid] = fc_w[tid];

    // packed xs byte-offsets per pair: low16 = i*260, high16 = j*260
    for (int p = tid; p < NPAD; p += THREADS) {
        uint32_t o = 0;
        if (p < NP) {
            int i = 0, rem = p;
            while (rem >= NF - 1 - i) { rem -= NF - 1 - i; ++i; }
            int j = i + 1 + rem;
            o = (uint32_t)(i * 260) | ((uint32_t)(j * 260) << 16);
        }
        offs[p] = o;
    }
    const float pb = proj_b[0];
    __syncthreads();

    // ---- Phase 2: chunked tiled GEMM ----
    const int w  = wid;          // col-group: cols 4w..4w+3
    const int pg = lane;         // pair-group within chunk: pairs 4pg..4pg+3
    const float4* ipv4 = (const float4*)(smem + IP_OFF);
    const ulonglong2* W2v = (const ulonglong2*)(smem + W2_OFF);
    const uint4* offs4 = (const uint4*)(smem + OFFS_OFF);
    const char* xsc = (const char*)xs;

    const float pw0 = pw_s[4 * w + 0], pw1 = pw_s[4 * w + 1];
    const float pw2 = pw_s[4 * w + 2], pw3 = pw_s[4 * w + 3];

    for (int t = 0; t < NCH; ++t) {
        const int cbase = t * CP;

        // ---- build IP tile: thread handles 4 pairs x 1 d, 8 d's per thread ----
        {
            const uint4 oo = offs4[t * 32 + pg];   // 4 pairs' packed offsets
#pragma unroll
            for (int it = 0; it < 8; ++it) {
                const int d = wid + it * 8;
                const char* xsd = xsc + d * 4;
                float4 pr;
                pr.x = *(const float*)(xsd + (oo.x & 0xffffu)) * *(const float*)(xsd + (oo.x >> 16));
                pr.y = *(const float*)(xsd + (oo.y & 0xffffu)) * *(const float*)(xsd + (oo.y >> 16));
                pr.z = *(const float*)(xsd + (oo.z & 0xffffu)) * *(const float*)(xsd + (oo.z >> 16));
                pr.w = *(const float*)(xsd + (oo.w & 0xffffu)) * *(const float*)(xsd + (oo.w >> 16));
                *(float4*)(smem + IP_OFF + d * 512 + pg * 16) = pr;
            }
        }
        __syncthreads();

        // ---- GEMM: 4 pairs x 4 cols per thread, K=64 ----
        unsigned long long acc[4][2];
        {
            const unsigned long long b01 = pack2(ab_s[4 * w], ab_s[4 * w + 1]);
            const unsigned long long b23 = pack2(ab_s[4 * w + 2], ab_s[4 * w + 3]);
#pragma unroll
            for (int p = 0; p < 4; ++p) { acc[p][0] = b01; acc[p][1] = b23; }
        }
#pragma unroll 16
        for (int d = 0; d < ED; ++d) {
            const float4 ip = ipv4[d * 32 + pg];
            const ulonglong2 wv = W2v[d * 8 + w];
            unsigned long long s0 = splat2(ip.x);
            unsigned long long s1 = splat2(ip.y);
            unsigned long long s2 = splat2(ip.z);
            unsigned long long s3 = splat2(ip.w);
            FMA2(acc[0][0], s0, wv.x); FMA2(acc[0][1], s0, wv.y);
            FMA2(acc[1][0], s1, wv.x); FMA2(acc[1][1], s1, wv.y);
            FMA2(acc[2][0], s2, wv.x); FMA2(acc[2][1], s2, wv.y);
            FMA2(acc[3][0], s3, wv.x); FMA2(acc[3][1], s3, wv.y);
        }

        // ---- epilogue: relu + proj partial per pair ----
#pragma unroll
        for (int p = 0; p < 4; ++p) {
            float a0, a1, a2, a3;
            unpack2(acc[p][0], a0, a1);
            unpack2(acc[p][1], a2, a3);
            float lg = fmaxf(a0, 0.f) * pw0 + fmaxf(a1, 0.f) * pw1 +
                       fmaxf(a2, 0.f) * pw2 + fmaxf(a3, 0.f) * pw3;
            part[(4 * pg + p) * 9 + w] = lg;
        }
        __syncthreads();

        // ---- reduce 8 col-group partials -> logit ----
        if (tid < CP) {
            const int p = cbase + tid;
            if (p < NP) {
                float s = pb;
#pragma unroll
                for (int k = 0; k < 8; ++k) s += part[tid * 9 + k];
                logits_s[p] = s;
            }
        }
        // no extra sync: next build writes IP only; sync after build protects part
    }
    __syncthreads();

    // ---- Phase 3: softmax over 780 (unnormalized; fold 1/S at end) ----
    float lm = -3.4e38f;
    for (int p = tid; p < NP; p += THREADS) lm = fmaxf(lm, logits_s[p]);
#pragma unroll
    for (int o = 16; o > 0; o >>= 1) lm = fmaxf(lm, __shfl_xor_sync(0xffffffffu, lm, o));
    if (lane == 0) rmax[wid] = lm;
    __syncthreads();

    float gmax = rmax[0];
#pragma unroll
    for (int wq = 1; wq < 8; ++wq) gmax = fmaxf(gmax, rmax[wq]);

    float ls = 0.f;
    for (int p = tid; p < NP; p += THREADS) {
        float e = __expf(logits_s[p] - gmax);
        logits_s[p] = e;
        ls += e;
    }
#pragma unroll
    for (int o = 16; o > 0; o >>= 1) ls += __shfl_xor_sync(0xffffffffu, ls, o);
    if (lane == 0) rsum[wid] = ls;
    __syncthreads();

    // ---- Phase 4: weighted sum over pairs (recompute ip), fc dot ----
    float* part4 = (float*)(smem + IP_OFF);   // 8 warps x 64 dims (IP tile is dead)
    float accL = 0.f, accH = 0.f;
    for (int p = wid; p < NP; p += 8) {
        const float s = logits_s[p];
        const uint32_t o = offs[p];
        const char* xi = xsc + (o & 0xffffu);
        const char* xj = xsc + (o >> 16);
        accL += s * (*(const float*)(xi + lane * 4)       * *(const float*)(xj + lane * 4));
        accH += s * (*(const float*)(xi + 128 + lane * 4) * *(const float*)(xj + 128 + lane * 4));
    }
    part4[wid * 64 + lane]      = accL;
    part4[wid * 64 + 32 + lane] = accH;
    __syncthreads();

    if (tid < 64) {
        float v = 0.f;
#pragma unroll
        for (int wq = 0; wq < 8; ++wq) v += part4[wq * 64 + tid];
        red_s[tid] = v * fw_s[tid];
    }
    __syncthreads();

    if (tid == 0) {
        float S = 0.f;
#pragma unroll
        for (int wq = 0; wq < 8; ++wq) S += rsum[wq];
        float tt = 0.f;
#pragma unroll
        for (int k = 0; k < 64; ++k) tt += red_s[k];
        out[b] = tt / S + fc_b[0];
    }
}

extern "C" void kernel_launch(void* const* d_in, const int* in_sizes, int n_in,
                              void* d_out, int out_size)
{
    const float* x      = (const float*)d_in[0];
    const float* attn_w = (const float*)d_in[1];
    const float* attn_b = (const float*)d_in[2];
    const float* proj_w = (const float*)d_in[3];
    const float* proj_b = (const float*)d_in[4];
    const float* fc_w   = (const float*)d_in[5];
    const float* fc_b   = (const float*)d_in[6];
    float* out = (float*)d_out;

    cudaFuncSetAttribute(afm_kernel, cudaFuncAttributeMaxDynamicSharedMemorySize, SMEM_TOTAL);
    afm_kernel<<<2048, THREADS, SMEM_TOTAL>>>(x, attn_w, attn_b, proj_w, proj_b, fc_w, fc_b, out);
}